// round 14
// baseline (speedup 1.0000x reference)
#include <cuda_runtime.h>
#include <cstdint>
#include <cstddef>

#define N_FEAT 20000
#define BINS   64
#define DOUT   256
#define BATCH  4096
#define TILE_N 160
#define TILE_H 80                     // per-thread q-range (half of TILE_N)
#define NBLK   125                    // 125 * 160 == 20000 exactly, single wave
#define MASKW  ((N_FEAT + 31) / 32)   // 625

#define LOG10A   2.302585093f
#define CLIP_LO -16.11809565f         // log(1e-7)
#define CLIP_HI -1.00000005e-7f       // log(0.9999999)
#define INV_T    (1.0f / 9.9999f)

typedef unsigned long long u64;

// Scratch (static device globals — no runtime allocation)
__device__ float    g_sc[N_FEAT];                  // column log-softmax constants
__device__ float    g_pSum[DOUT * NBLK];           // [d][b] partial sum exp(t)
__device__ u64      g_top4p[DOUT * NBLK * 4];      // [d][b][4] per-block top-4
__device__ u64      g_top4[DOUT * 4];              // merged per-row top-4
__device__ float    g_logZ[DOUT];
__device__ unsigned g_pair[DOUT];                  // sorted (y<<8)|d

__device__ __forceinline__ float negInf() { return __int_as_float(0xff800000); }

__device__ __forceinline__ void pairMax(float& v, int& i, float ov, int oi) {
    if (ov > v || (ov == v && oi < i)) { v = ov; i = oi; }
}
__device__ __forceinline__ void warpReducePair(float& v, int& i) {
    #pragma unroll
    for (int off = 16; off; off >>= 1) {
        float ov = __shfl_down_sync(0xffffffffu, v, off);
        int   oi = __shfl_down_sync(0xffffffffu, i, off);
        pairMax(v, i, ov, oi);
    }
}
__device__ __forceinline__ u64 pack2(float a, float b) {
    u64 r;
    asm("mov.b64 %0, {%1, %2};" : "=l"(r) : "f"(a), "f"(b));
    return r;
}
__device__ __forceinline__ void unpack2(u64 p, float& a, float& b) {
    asm("mov.b64 {%0, %1}, %2;" : "=f"(a), "=f"(b) : "l"(p));
}
// monotone float->u32 (order-preserving)
__device__ __forceinline__ unsigned monoKey(float f) {
    unsigned u = __float_as_uint(f);
    return (u & 0x80000000u) ? ~u : (u | 0x80000000u);
}
__device__ __forceinline__ float unMono(unsigned m) {
    unsigned u = (m & 0x80000000u) ? (m ^ 0x80000000u) : ~m;
    return __uint_as_float(u);
}
// accurate -log(u): series for u near 1 (winners live there), __logf otherwise
__device__ __forceinline__ float neglog_acc(float u) {
    float w  = 1.0f - u;
    float xs = w * (1.0f + w * (0.5f + w * (0.333333333f + w * 0.25f)));
    float xb = -__logf(u);
    return (w < 0.09f) ? xs : xb;
}
// insert into descending sorted top-4 (c0 >= c1 >= c2 >= c3)
__device__ __forceinline__ void ins4(u64& c0, u64& c1, u64& c2, u64& c3, u64 cc) {
    if (cc > c3) {
        if (cc > c1) {
            if (cc > c0) { c3 = c2; c2 = c1; c1 = c0; c0 = cc; }
            else         { c3 = c2; c2 = c1; c1 = cc; }
        } else {
            if (cc > c2) { c3 = c2; c2 = cc; }
            else         c3 = cc;
        }
    }
}
__device__ __forceinline__ u64 warpMax64(u64 h) {
    u64 m = h;
    #pragma unroll
    for (int off = 16; off; off >>= 1) {
        u64 o = __shfl_xor_sync(0xffffffffu, m, off);
        if (o > m) m = o;
    }
    return m;
}

#define FFMA2(acc, va, vb) \
    asm("fma.rn.f32x2 %0, %1, %2, %0;" : "+l"(acc) : "l"(va), "l"(vb))

// ---------------------------------------------------------------------------
// Kernel 1 (256 threads, T_d=2 register tiling): thread (c=tid&127, half)
// owns d-columns c and c+128 over half the n-range. Each LDS.128 of u now
// feeds 4 FFMA2 (was 2) -> Stage A shared-load count halves (k1 was
// LDS-issue bound: 20480 broadcast LDS.128/block at ~4cyc ≈ its duration).
// Per-element math order bitwise identical to R13 (even/odd-k FFMA2 split,
// same Stage B/C reduction orders).
// ---------------------------------------------------------------------------
__global__ void __launch_bounds__(256, 1)
k_compute_t(const float* __restrict__ u, const float* __restrict__ tinyW,
            const float* __restrict__ uniform)
{
    extern __shared__ float sm[];
    float* u_s  = sm;                          // 160*64, row-major [n][k]
    float* tile = sm + TILE_N * BINS;          // 256 * 161 (padded): m values
    float* s_c  = tile + DOUT * (TILE_N + 1);  // 160: log(sum_d exp(m))

    const int tid  = threadIdx.x;
    const int lid  = tid & 31;
    const int wid  = tid >> 5;                 // 0..7
    const int bid  = blockIdx.x;
    const int n0   = bid * TILE_N;
    const int TS   = TILE_N + 1;
    const int c    = tid & 127;                // d0 = c, d1 = c + 128
    const int half = tid >> 7;                 // 0/1: which n-half of GEMM

    // weights for BOTH columns, packed K-pairs {w[2k],w[2k+1]} -> 64 u64 regs
    u64 wpa[BINS / 2], wpb[BINS / 2];
    #pragma unroll
    for (int k2 = 0; k2 < BINS / 2; ++k2) {
        wpa[k2] = pack2(tinyW[(2 * k2) * DOUT + c],
                        tinyW[(2 * k2 + 1) * DOUT + c]);
        wpb[k2] = pack2(tinyW[(2 * k2) * DOUT + c + 128],
                        tinyW[(2 * k2 + 1) * DOUT + c + 128]);
    }

    // u tile load, float4 (2560 float4, 10 per thread)
    {
        const float4* u4 = (const float4*)(u + (size_t)n0 * BINS);
        float4* s4 = (float4*)u_s;
        #pragma unroll
        for (int i = tid; i < TILE_N * BINS / 4; i += 256) s4[i] = u4[i];
    }
    __syncthreads();

    // Stage A: GEMM, 4 n x 2 d per step (8 independent FFMA2 chains), K-SIMD.
    {
        const ulonglong2* uv = (const ulonglong2*)u_s;   // 16B = 4 floats = 2 k-pairs
        const int q0 = half * TILE_H;
        for (int q = q0; q < q0 + TILE_H; q += 4) {
            u64 a0 = 0ull, a1 = 0ull, a2 = 0ull, a3 = 0ull;   // column c
            u64 b0 = 0ull, b1 = 0ull, b2 = 0ull, b3 = 0ull;   // column c+128
            #pragma unroll
            for (int k4 = 0; k4 < BINS / 4; ++k4) {
                ulonglong2 v0 = uv[(q + 0) * (BINS / 4) + k4];
                ulonglong2 v1 = uv[(q + 1) * (BINS / 4) + k4];
                ulonglong2 v2 = uv[(q + 2) * (BINS / 4) + k4];
                ulonglong2 v3 = uv[(q + 3) * (BINS / 4) + k4];
                FFMA2(a0, v0.x, wpa[2 * k4]);     FFMA2(b0, v0.x, wpb[2 * k4]);
                FFMA2(a1, v1.x, wpa[2 * k4]);     FFMA2(b1, v1.x, wpb[2 * k4]);
                FFMA2(a2, v2.x, wpa[2 * k4]);     FFMA2(b2, v2.x, wpb[2 * k4]);
                FFMA2(a3, v3.x, wpa[2 * k4]);     FFMA2(b3, v3.x, wpb[2 * k4]);
                FFMA2(a0, v0.y, wpa[2 * k4 + 1]); FFMA2(b0, v0.y, wpb[2 * k4 + 1]);
                FFMA2(a1, v1.y, wpa[2 * k4 + 1]); FFMA2(b1, v1.y, wpb[2 * k4 + 1]);
                FFMA2(a2, v2.y, wpa[2 * k4 + 1]); FFMA2(b2, v2.y, wpb[2 * k4 + 1]);
                FFMA2(a3, v3.y, wpa[2 * k4 + 1]); FFMA2(b3, v3.y, wpb[2 * k4 + 1]);
            }
            float lo, hi;
            unpack2(a0, lo, hi); tile[c * TS + q + 0] = lo + hi;
            unpack2(a1, lo, hi); tile[c * TS + q + 1] = lo + hi;
            unpack2(a2, lo, hi); tile[c * TS + q + 2] = lo + hi;
            unpack2(a3, lo, hi); tile[c * TS + q + 3] = lo + hi;
            unpack2(b0, lo, hi); tile[(c + 128) * TS + q + 0] = lo + hi;
            unpack2(b1, lo, hi); tile[(c + 128) * TS + q + 1] = lo + hi;
            unpack2(b2, lo, hi); tile[(c + 128) * TS + q + 2] = lo + hi;
            unpack2(b3, lo, hi); tile[(c + 128) * TS + q + 3] = lo + hi;
        }
    }
    __syncthreads();

    // Stage B: column constants, warp-parallel over 8 warps (20 cols each).
    // Row-strided reads conflict-free: TS=161 ≡ 1 (mod 32). Same inner
    // summation order as R13 -> bitwise identical s_c.
    for (int n = wid; n < TILE_N; n += 8) {
        float s = 0.f;
        #pragma unroll
        for (int jj = 0; jj < 8; ++jj)
            s += __expf(tile[(lid + 32 * jj) * TS + n]);
        #pragma unroll
        for (int off = 16; off; off >>= 1)
            s += __shfl_xor_sync(0xffffffffu, s, off);
        if (lid == 0) {
            float cc = __logf(s);
            s_c[n] = cc;
            g_sc[n0 + n] = cc;
        }
    }
    __syncthreads();

    // Stage C: per-row t in registers; partial sum exp(t) + per-block top-4.
    // Warp wid handles rows wid*32 .. wid*32+31 (same per-row order as R13).
    for (int r = 0; r < 32; ++r) {
        const int dd = wid * 32 + r;
        float s = 0.f;
        u64 c0 = 0, c1 = 0, c2 = 0, c3 = 0;
        #pragma unroll
        for (int j = 0; j < TILE_N / 32; ++j) {
            const int n = j * 32 + lid;
            float m   = tile[dd * TS + n];
            float lal = fminf(fmaxf(m - s_c[n], CLIP_LO), CLIP_HI);
            float uu  = uniform[(size_t)dd * N_FEAT + n0 + n];
            float x   = neglog_acc(uu);        // -log(u), winner-exact
            float gum = -__logf(x);            // abs-accurate everywhere
            float t   = (LOG10A + lal + gum) * INV_T;
            s += __expf(t);
            u64 cc = ((u64)monoKey(t) << 32) | (0xffffffffu - (unsigned)(n0 + n));
            ins4(c0, c1, c2, c3, cc);
        }
        #pragma unroll
        for (int off = 16; off; off >>= 1) s += __shfl_down_sync(0xffffffffu, s, off);
        if (lid == 0) g_pSum[dd * NBLK + bid] = s;

        // warp top-4: 4 rounds of warp-argmax with per-lane head advance
        int pr = 0;
        #pragma unroll
        for (int rd = 0; rd < 4; ++rd) {
            u64 h = (pr == 0) ? c0 : (pr == 1) ? c1 : (pr == 2) ? c2 : (pr == 3) ? c3 : 0ull;
            u64 m = warpMax64(h);
            if (h == m && h != 0ull) pr++;
            if (lid == 0) g_top4p[((size_t)dd * NBLK + bid) * 4 + rd] = m;
        }
    }
}

// ---------------------------------------------------------------------------
// Kernel 2: parallel merge of per-block partials (one block per row).
// Global top-4 is a subset of the union of block top-4s.
// ---------------------------------------------------------------------------
__global__ void __launch_bounds__(128)
k_merge()
{
    const int d   = blockIdx.x;
    const int tid = threadIdx.x;
    const int lid = tid & 31;
    const int wid = tid >> 5;
    __shared__ float sS[4];
    __shared__ u64 sW[4];
    __shared__ u64 sWin;

    // logZ from 125 partials
    float s = (tid < NBLK) ? g_pSum[d * NBLK + tid] : 0.f;
    #pragma unroll
    for (int off = 16; off; off >>= 1) s += __shfl_down_sync(0xffffffffu, s, off);
    if (lid == 0) sS[wid] = s;
    __syncthreads();
    if (tid == 0) g_logZ[d] = __logf((sS[0] + sS[1]) + (sS[2] + sS[3]));

    // thread tid owns block tid's sorted-4 list (tid < NBLK)
    u64 lst[4] = {0, 0, 0, 0};
    if (tid < NBLK) {
        #pragma unroll
        for (int j = 0; j < 4; ++j) lst[j] = g_top4p[((size_t)d * NBLK + tid) * 4 + j];
    }
    int pr = 0;
    for (int r = 0; r < 4; ++r) {
        u64 h = (pr < 4) ? lst[pr] : 0ull;
        u64 m = warpMax64(h);
        if (lid == 0) sW[wid] = m;
        __syncthreads();
        if (tid == 0) {
            u64 w = sW[0];
            if (sW[1] > w) w = sW[1];
            if (sW[2] > w) w = sW[2];
            if (sW[3] > w) w = sW[3];
            sWin = w;
            g_top4[d * 4 + r] = w;
        }
        __syncthreads();
        if (pr < 4 && h == sWin && h != 0ull) pr++;
        __syncthreads();
    }
}

// ---------------------------------------------------------------------------
// Kernel 3: greedy selection via sorted sweep with candidate fallback.
// Fallback (P ~ 1e-7): EXACT recompute of the row's t (same even/odd fmaf
// summation order as the FFMA2 GEMM, stored g_sc, same gumbel sequence).
// Epilogue: sort (y<<8|d) ascending for gather locality.
// Produces the EXACT greedy sequence (incl. flat-argmax tie-breaks).
// ---------------------------------------------------------------------------
__global__ void __launch_bounds__(256)
k_select(const float* __restrict__ u, const float* __restrict__ tinyW,
         const float* __restrict__ uniform)
{
    __shared__ u64  sC[DOUT];        // sorted composites (ascending)
    __shared__ u64  cand[DOUT][4];
    __shared__ int  sArg[DOUT];      // current proposed column per row
    __shared__ int  sPtr[DOUT];      // next unused candidate
    __shared__ int  sSel[DOUT];      // committed column per row
    __shared__ float sLz[DOUT];
    __shared__ unsigned sMask[MASKW];
    __shared__ unsigned sPair[DOUT];
    __shared__ float sWf[BINS];      // fallback weights
    __shared__ u64  pC[16];          // pending composites
    __shared__ int  sCmd, sRrow, sI, sP;
    __shared__ float redV[8]; __shared__ int redI[8];

    const int tid = threadIdx.x;
    const int lid = tid & 31;
    const int wid = tid >> 5;

    // init per-row state (top4 + logZ merged in parallel by k_merge)
    {
        u64 cd0 = g_top4[tid * 4 + 0];
        cand[tid][0] = cd0;
        cand[tid][1] = g_top4[tid * 4 + 1];
        cand[tid][2] = g_top4[tid * 4 + 2];
        cand[tid][3] = g_top4[tid * 4 + 3];
        float lz = g_logZ[tid];
        sLz[tid]  = lz;
        sArg[tid] = (int)(0xffffffffu - (unsigned)(cd0 & 0xffffffffu));
        sPtr[tid] = 1;
        float key = unMono((unsigned)(cd0 >> 32)) - lz;
        sC[tid] = ((u64)monoKey(key) << 32) | (unsigned)(255 - tid);
    }
    for (int i = tid; i < MASKW; i += 256) sMask[i] = 0u;
    if (tid == 0) { sI = 0; sP = 0; sCmd = 0; }
    __syncthreads();

    // bitonic sort ascending (rank r lives at index 255-r)
    for (int k = 2; k <= 256; k <<= 1) {
        for (int j = k >> 1; j > 0; j >>= 1) {
            int ixj = tid ^ j;
            if (ixj > tid) {
                u64 a = sC[tid], b = sC[ixj];
                bool sw = ((tid & k) == 0) ? (a > b) : (a < b);
                if (sw) { sC[tid] = b; sC[ixj] = a; }
            }
            __syncthreads();
        }
    }

    // sweep
    while (true) {
        if (wid == 0) {
            int i = sI, P = sP;
            int cmd = 0;
            while (true) {
                i = __shfl_sync(0xffffffffu, i, 0);
                P = __shfl_sync(0xffffffffu, P, 0);
                if (i >= 256 && P == 0) { cmd = 2; break; }
                if (P == 0) {
                    // chunked commit of up to 32 ranks
                    int r = i + lid;
                    bool valid = r < 256;
                    u64 C = valid ? sC[255 - r] : 0ull;
                    int row = 255 - (int)(C & 0xffffffffu);
                    int a   = valid ? sArg[row] : -1;
                    bool bad = false;
                    unsigned validmask = __ballot_sync(0xffffffffu, valid);
                    unsigned peers = __match_any_sync(0xffffffffu, a) & validmask;
                    if (valid) {
                        bool masked = (sMask[a >> 5] >> (a & 31)) & 1u;
                        bool first  = (peers & ((1u << lid) - 1u)) == 0;
                        bad = masked || !first;
                    }
                    unsigned badmask = __ballot_sync(0xffffffffu, valid && bad);
                    int cb = badmask ? ((int)__ffs(badmask) - 1) : 32;
                    int ncommit = min(cb, 256 - i);
                    if (lid < ncommit) {
                        atomicOr(&sMask[a >> 5], 1u << (a & 31));
                        sSel[row] = a;
                    }
                    __syncwarp();
                    i += ncommit;
                    if (cb < 32 && i < 256) {
                        // rank i is bad: pop next candidate or fallback
                        u64 Cc = sC[255 - i];
                        int brow = 255 - (int)(Cc & 0xffffffffu);
                        i += 1;
                        int act = 0;
                        if (lid == 0) {
                            int ptr = sPtr[brow];
                            if (ptr < 4 && P < 15) {
                                u64 cd = cand[brow][ptr];
                                sPtr[brow] = ptr + 1;
                                sArg[brow] = (int)(0xffffffffu - (unsigned)(cd & 0xffffffffu));
                                float nk = unMono((unsigned)(cd >> 32)) - sLz[brow];
                                pC[P] = ((u64)monoKey(nk) << 32) | (unsigned)(255 - brow);
                                P = P + 1;
                            } else {
                                sRrow = brow;
                                act = 1;
                            }
                        }
                        act = __shfl_sync(0xffffffffu, act, 0);
                        if (act) { cmd = 1; break; }
                    }
                } else {
                    // serial merge: sorted head vs best pending (lane 0)
                    int act = 0;
                    if (lid == 0) {
                        bool haveS = i < 256;
                        u64 Cs = haveS ? sC[255 - i] : 0ull;
                        int bj = 0; u64 Cb = pC[0];
                        for (int j = 1; j < P; ++j)
                            if (pC[j] > Cb) { Cb = pC[j]; bj = j; }
                        bool pickP = !haveS || (Cb > Cs);
                        u64 C = pickP ? Cb : Cs;
                        int row = 255 - (int)(C & 0xffffffffu);
                        int a = sArg[row];
                        bool masked = (sMask[a >> 5] >> (a & 31)) & 1u;
                        if (pickP) { pC[bj] = pC[P - 1]; P--; }
                        else i++;
                        if (!masked) {
                            sMask[a >> 5] |= 1u << (a & 31);
                            sSel[row] = a;
                        } else {
                            int ptr = sPtr[row];
                            if (ptr < 4 && P < 15) {
                                u64 cd = cand[row][ptr];
                                sPtr[row] = ptr + 1;
                                sArg[row] = (int)(0xffffffffu - (unsigned)(cd & 0xffffffffu));
                                float nk = unMono((unsigned)(cd >> 32)) - sLz[row];
                                pC[P] = ((u64)monoKey(nk) << 32) | (unsigned)(255 - row);
                                P = P + 1;
                            } else {
                                sRrow = row;
                                act = 1;
                            }
                        }
                    }
                    act = __shfl_sync(0xffffffffu, act, 0);
                    if (act) { cmd = 1; break; }
                }
            }
            if (lid == 0) { sCmd = cmd; sI = i; sP = P; }
        }
        __syncthreads();
        if (sCmd == 2) break;

        // ---- fallback: exact recompute of row t over unmasked columns ----
        {
            const int row = sRrow;
            if (tid < BINS) sWf[tid] = tinyW[tid * DOUT + row];
            __syncthreads();
            float bv = negInf(); int bi = 0x7fffffff;
            for (int n = tid; n < N_FEAT; n += 256) {
                if (!((sMask[n >> 5] >> (n & 31)) & 1u)) {
                    const float* ur = u + (size_t)n * BINS;
                    float aE = 0.f, aO = 0.f;   // same even/odd order as FFMA2 GEMM
                    #pragma unroll
                    for (int k2 = 0; k2 < BINS / 2; ++k2) {
                        aE = fmaf(ur[2 * k2],     sWf[2 * k2],     aE);
                        aO = fmaf(ur[2 * k2 + 1], sWf[2 * k2 + 1], aO);
                    }
                    float m   = aE + aO;
                    float lal = fminf(fmaxf(m - g_sc[n], CLIP_LO), CLIP_HI);
                    float uu  = uniform[(size_t)row * N_FEAT + n];
                    float x   = neglog_acc(uu);
                    float gum = -__logf(x);
                    float t   = (LOG10A + lal + gum) * INV_T;
                    if (t > bv) { bv = t; bi = n; }
                }
            }
            warpReducePair(bv, bi);
            if (lid == 0) { redV[wid] = bv; redI[wid] = bi; }
            __syncthreads();
            if (tid < 32) {
                bv = (tid < 8) ? redV[tid] : negInf();
                bi = (tid < 8) ? redI[tid] : 0x7fffffff;
                warpReducePair(bv, bi);
                if (tid == 0) {
                    sArg[row] = bi;
                    sPtr[row] = 4;   // stays list-exhausted
                    float nk = bv - sLz[row];
                    pC[sP] = ((u64)monoKey(nk) << 32) | (unsigned)(255 - row);
                    sP = sP + 1;
                    sCmd = 0;
                }
            }
        }
        __syncthreads();
    }

    // epilogue: sort (y<<8 | d) ascending for gather locality
    __syncthreads();
    sPair[tid] = ((unsigned)sSel[tid] << 8) | (unsigned)tid;
    __syncthreads();
    for (int k = 2; k <= 256; k <<= 1) {
        for (int j = k >> 1; j > 0; j >>= 1) {
            int ixj = tid ^ j;
            if (ixj > tid) {
                unsigned a = sPair[tid], b = sPair[ixj];
                bool sw = ((tid & k) == 0) ? (a > b) : (a < b);
                if (sw) { sPair[tid] = b; sPair[ixj] = a; }
            }
            __syncthreads();
        }
    }
    g_pair[tid] = sPair[tid];
}

// ---------------------------------------------------------------------------
// Kernel 4: Y[b,d] = X[b, y] — one b-row per block. Measured best across
// GB=1/4/8 (21.2 / 21.9 / 22.8 us): gather is DRAM 128B-line-fill bound,
// extra per-thread MLP only costs occupancy.
// ---------------------------------------------------------------------------
__global__ void __launch_bounds__(256)
k_gather(const float* __restrict__ X, float* __restrict__ Y)
{
    const unsigned p = g_pair[threadIdx.x];
    const int b = blockIdx.x;
    Y[(size_t)b * DOUT + (p & 255u)] = X[(size_t)b * N_FEAT + (p >> 8)];
}

extern "C" void kernel_launch(void* const* d_in, const int* in_sizes, int n_in,
                              void* d_out, int out_size)
{
    const float* X       = (const float*)d_in[0];
    const float* u       = (const float*)d_in[1];
    const float* tinyW   = (const float*)d_in[2];
    const float* uniform = (const float*)d_in[3];
    float* Y = (float*)d_out;

    const int smem = (TILE_N * BINS + DOUT * (TILE_N + 1) + TILE_N) * (int)sizeof(float);
    cudaFuncSetAttribute(k_compute_t, cudaFuncAttributeMaxDynamicSharedMemorySize, smem);

    k_compute_t<<<NBLK, 256, smem>>>(u, tinyW, uniform);
    k_merge<<<DOUT, 128>>>();
    k_select<<<1, 256>>>(u, tinyW, uniform);
    k_gather<<<BATCH, 256>>>(X, Y);
}

// round 15
// speedup vs baseline: 1.1228x; 1.1228x over previous
#include <cuda_runtime.h>
#include <cstdint>
#include <cstddef>

#define N_FEAT 20000
#define BINS   64
#define DOUT   256
#define BATCH  4096
#define TILE_N 160
#define TILE_H 80                     // TILE_N/2, per-thread q-range
#define NBLK   125                    // 125 * 160 == 20000 exactly, single wave
#define MASKW  ((N_FEAT + 31) / 32)   // 625

#define LOG10A   2.302585093f
#define CLIP_LO -16.11809565f         // log(1e-7)
#define CLIP_HI -1.00000005e-7f       // log(0.9999999)
#define INV_T    (1.0f / 9.9999f)

typedef unsigned long long u64;

// Scratch (static device globals — no runtime allocation)
__device__ float    g_sc[N_FEAT];                  // column log-softmax constants
__device__ float    g_pSum[DOUT * NBLK];           // [d][b] partial sum exp(t)
__device__ u64      g_top4p[DOUT * NBLK * 4];      // [d][b][4] per-block top-4
__device__ u64      g_top4[DOUT * 4];              // merged per-row top-4
__device__ float    g_logZ[DOUT];
__device__ unsigned g_pair[DOUT];                  // sorted (y<<8)|d

__device__ __forceinline__ float negInf() { return __int_as_float(0xff800000); }

__device__ __forceinline__ void pairMax(float& v, int& i, float ov, int oi) {
    if (ov > v || (ov == v && oi < i)) { v = ov; i = oi; }
}
__device__ __forceinline__ void warpReducePair(float& v, int& i) {
    #pragma unroll
    for (int off = 16; off; off >>= 1) {
        float ov = __shfl_down_sync(0xffffffffu, v, off);
        int   oi = __shfl_down_sync(0xffffffffu, i, off);
        pairMax(v, i, ov, oi);
    }
}
__device__ __forceinline__ u64 pack2(float a, float b) {
    u64 r;
    asm("mov.b64 %0, {%1, %2};" : "=l"(r) : "f"(a), "f"(b));
    return r;
}
__device__ __forceinline__ void unpack2(u64 p, float& a, float& b) {
    asm("mov.b64 {%0, %1}, %2;" : "=f"(a), "=f"(b) : "l"(p));
}
// monotone float->u32 (order-preserving)
__device__ __forceinline__ unsigned monoKey(float f) {
    unsigned u = __float_as_uint(f);
    return (u & 0x80000000u) ? ~u : (u | 0x80000000u);
}
__device__ __forceinline__ float unMono(unsigned m) {
    unsigned u = (m & 0x80000000u) ? (m ^ 0x80000000u) : ~m;
    return __uint_as_float(u);
}
// accurate -log(u): series for u near 1 (winners live there), __logf otherwise
__device__ __forceinline__ float neglog_acc(float u) {
    float w  = 1.0f - u;
    float xs = w * (1.0f + w * (0.5f + w * (0.333333333f + w * 0.25f)));
    float xb = -__logf(u);
    return (w < 0.09f) ? xs : xb;
}
// insert into descending sorted top-4 (c0 >= c1 >= c2 >= c3)
__device__ __forceinline__ void ins4(u64& c0, u64& c1, u64& c2, u64& c3, u64 cc) {
    if (cc > c3) {
        if (cc > c1) {
            if (cc > c0) { c3 = c2; c2 = c1; c1 = c0; c0 = cc; }
            else         { c3 = c2; c2 = c1; c1 = cc; }
        } else {
            if (cc > c2) { c3 = c2; c2 = cc; }
            else         c3 = cc;
        }
    }
}
__device__ __forceinline__ u64 warpMax64(u64 h) {
    u64 m = h;
    #pragma unroll
    for (int off = 16; off; off >>= 1) {
        u64 o = __shfl_xor_sync(0xffffffffu, m, off);
        if (o > m) m = o;
    }
    return m;
}

// ---------------------------------------------------------------------------
// Kernel 1 (512 threads): m = u @ tinyW (K-SIMD FFMA2), column log-softmax
// constant -> g_sc, per-row t computed IN REGISTERS ONLY: per-block partials
// (sum exp t, top-4 composites) written; t itself is never stored.
// (R11/R12/R14 lessons: this 512-thread shape is the local optimum —
// retiles, fused merges, and T_d=2 register tiling all regressed.)
// ---------------------------------------------------------------------------
__global__ void __launch_bounds__(512, 1)
k_compute_t(const float* __restrict__ u, const float* __restrict__ tinyW,
            const float* __restrict__ uniform)
{
    extern __shared__ float sm[];
    float* u_s  = sm;                          // 160*64, row-major [n][k]
    float* tile = sm + TILE_N * BINS;          // 256 * 161 (padded): m values
    float* s_c  = tile + DOUT * (TILE_N + 1);  // 160: log(sum_d exp(m))

    const int tid  = threadIdx.x;
    const int lid  = tid & 31;
    const int wid  = tid >> 5;                 // 0..15
    const int bid  = blockIdx.x;
    const int n0   = bid * TILE_N;
    const int TS   = TILE_N + 1;
    const int d    = tid & 255;
    const int half = tid >> 8;                 // 0/1: which n-half of GEMM

    // weights for column d, packed K-pairs {w[2k],w[2k+1]} -> 32 u64 regs
    u64 wp2[BINS / 2];
    #pragma unroll
    for (int k2 = 0; k2 < BINS / 2; ++k2)
        wp2[k2] = pack2(tinyW[(2 * k2) * DOUT + d], tinyW[(2 * k2 + 1) * DOUT + d]);

    // u tile load, float4 (160*64 floats = 2560 float4, 5 per thread)
    {
        const float4* u4 = (const float4*)(u + (size_t)n0 * BINS);
        float4* s4 = (float4*)u_s;
        #pragma unroll
        for (int i = tid; i < TILE_N * BINS / 4; i += 512) s4[i] = u4[i];
    }
    __syncthreads();

    // Stage A: GEMM, 4 n per step (independent FFMA2 chains), K-SIMD.
    // Thread handles its half of the q-range for column d.
    {
        const ulonglong2* uv = (const ulonglong2*)u_s;   // 16B = 4 floats = 2 k-pairs
        const int q0 = half * TILE_H;
        for (int q = q0; q < q0 + TILE_H; q += 4) {
            u64 a0 = 0ull, a1 = 0ull, a2 = 0ull, a3 = 0ull;
            #pragma unroll
            for (int k4 = 0; k4 < BINS / 4; ++k4) {
                ulonglong2 v0 = uv[(q + 0) * (BINS / 4) + k4];
                ulonglong2 v1 = uv[(q + 1) * (BINS / 4) + k4];
                ulonglong2 v2 = uv[(q + 2) * (BINS / 4) + k4];
                ulonglong2 v3 = uv[(q + 3) * (BINS / 4) + k4];
                asm("fma.rn.f32x2 %0, %1, %2, %0;" : "+l"(a0) : "l"(v0.x), "l"(wp2[2 * k4]));
                asm("fma.rn.f32x2 %0, %1, %2, %0;" : "+l"(a1) : "l"(v1.x), "l"(wp2[2 * k4]));
                asm("fma.rn.f32x2 %0, %1, %2, %0;" : "+l"(a2) : "l"(v2.x), "l"(wp2[2 * k4]));
                asm("fma.rn.f32x2 %0, %1, %2, %0;" : "+l"(a3) : "l"(v3.x), "l"(wp2[2 * k4]));
                asm("fma.rn.f32x2 %0, %1, %2, %0;" : "+l"(a0) : "l"(v0.y), "l"(wp2[2 * k4 + 1]));
                asm("fma.rn.f32x2 %0, %1, %2, %0;" : "+l"(a1) : "l"(v1.y), "l"(wp2[2 * k4 + 1]));
                asm("fma.rn.f32x2 %0, %1, %2, %0;" : "+l"(a2) : "l"(v2.y), "l"(wp2[2 * k4 + 1]));
                asm("fma.rn.f32x2 %0, %1, %2, %0;" : "+l"(a3) : "l"(v3.y), "l"(wp2[2 * k4 + 1]));
            }
            float lo, hi;
            unpack2(a0, lo, hi); tile[d * TS + q + 0] = lo + hi;
            unpack2(a1, lo, hi); tile[d * TS + q + 1] = lo + hi;
            unpack2(a2, lo, hi); tile[d * TS + q + 2] = lo + hi;
            unpack2(a3, lo, hi); tile[d * TS + q + 3] = lo + hi;
        }
    }
    __syncthreads();

    // Stage B: column constants, warp-parallel over all 16 warps (10 cols
    // each). Row-strided reads conflict-free: TS=161 ≡ 1 (mod 32).
    // No max-subtraction: |m| bounded ~2, exp safe.
    for (int n = wid; n < TILE_N; n += 16) {
        float s = 0.f;
        #pragma unroll
        for (int jj = 0; jj < 8; ++jj)
            s += __expf(tile[(lid + 32 * jj) * TS + n]);
        #pragma unroll
        for (int off = 16; off; off >>= 1)
            s += __shfl_xor_sync(0xffffffffu, s, off);
        if (lid == 0) {
            float c = __logf(s);
            s_c[n] = c;
            g_sc[n0 + n] = c;
        }
    }
    __syncthreads();

    // Stage C: per-row t in registers; partial sum exp(t) + per-block top-4.
    // Warp wid handles rows wid*16 .. wid*16+15.
    for (int r = 0; r < 16; ++r) {
        const int dd = wid * 16 + r;
        float s = 0.f;
        u64 c0 = 0, c1 = 0, c2 = 0, c3 = 0;
        #pragma unroll
        for (int j = 0; j < TILE_N / 32; ++j) {
            const int n = j * 32 + lid;
            float m   = tile[dd * TS + n];
            float lal = fminf(fmaxf(m - s_c[n], CLIP_LO), CLIP_HI);
            float uu  = uniform[(size_t)dd * N_FEAT + n0 + n];
            float x   = neglog_acc(uu);        // -log(u), winner-exact
            float gum = -__logf(x);            // abs-accurate everywhere
            float t   = (LOG10A + lal + gum) * INV_T;
            s += __expf(t);
            u64 cc = ((u64)monoKey(t) << 32) | (0xffffffffu - (unsigned)(n0 + n));
            ins4(c0, c1, c2, c3, cc);
        }
        #pragma unroll
        for (int off = 16; off; off >>= 1) s += __shfl_down_sync(0xffffffffu, s, off);
        if (lid == 0) g_pSum[dd * NBLK + bid] = s;

        // warp top-4: 4 rounds of warp-argmax with per-lane head advance
        int pr = 0;
        #pragma unroll
        for (int rd = 0; rd < 4; ++rd) {
            u64 h = (pr == 0) ? c0 : (pr == 1) ? c1 : (pr == 2) ? c2 : (pr == 3) ? c3 : 0ull;
            u64 m = warpMax64(h);
            if (h == m && h != 0ull) pr++;
            if (lid == 0) g_top4p[((size_t)dd * NBLK + bid) * 4 + rd] = m;
        }
    }
}

// ---------------------------------------------------------------------------
// Kernel 2: parallel merge of per-block partials (one block per row).
// PDL: launched with programmatic stream serialization; blocks dispatch
// during k1's tail and wait at the grid-dependency sync before reading.
// ---------------------------------------------------------------------------
__global__ void __launch_bounds__(128)
k_merge()
{
    cudaGridDependencySynchronize();   // wait for k1 completion + visibility

    const int d   = blockIdx.x;
    const int tid = threadIdx.x;
    const int lid = tid & 31;
    const int wid = tid >> 5;
    __shared__ float sS[4];
    __shared__ u64 sW[4];
    __shared__ u64 sWin;

    // logZ from 125 partials
    float s = (tid < NBLK) ? g_pSum[d * NBLK + tid] : 0.f;
    #pragma unroll
    for (int off = 16; off; off >>= 1) s += __shfl_down_sync(0xffffffffu, s, off);
    if (lid == 0) sS[wid] = s;
    __syncthreads();
    if (tid == 0) g_logZ[d] = __logf((sS[0] + sS[1]) + (sS[2] + sS[3]));

    // thread tid owns block tid's sorted-4 list (tid < NBLK)
    u64 lst[4] = {0, 0, 0, 0};
    if (tid < NBLK) {
        #pragma unroll
        for (int j = 0; j < 4; ++j) lst[j] = g_top4p[((size_t)d * NBLK + tid) * 4 + j];
    }
    int pr = 0;
    for (int r = 0; r < 4; ++r) {
        u64 h = (pr < 4) ? lst[pr] : 0ull;
        u64 m = warpMax64(h);
        if (lid == 0) sW[wid] = m;
        __syncthreads();
        if (tid == 0) {
            u64 w = sW[0];
            if (sW[1] > w) w = sW[1];
            if (sW[2] > w) w = sW[2];
            if (sW[3] > w) w = sW[3];
            sWin = w;
            g_top4[d * 4 + r] = w;
        }
        __syncthreads();
        if (pr < 4 && h == sWin && h != 0ull) pr++;
        __syncthreads();
    }
}

// ---------------------------------------------------------------------------
// Kernel 3: greedy selection via sorted sweep with candidate fallback.
// Fallback (P ~ 1e-7): EXACT recompute of the row's t (same even/odd fmaf
// summation order as the FFMA2 GEMM, stored g_sc, same gumbel sequence).
// Epilogue: sort (y<<8|d) ascending for gather locality.
// Produces the EXACT greedy sequence (incl. flat-argmax tie-breaks).
// ---------------------------------------------------------------------------
__global__ void __launch_bounds__(256)
k_select(const float* __restrict__ u, const float* __restrict__ tinyW,
         const float* __restrict__ uniform)
{
    cudaGridDependencySynchronize();   // wait for k_merge completion

    __shared__ u64  sC[DOUT];        // sorted composites (ascending)
    __shared__ u64  cand[DOUT][4];
    __shared__ int  sArg[DOUT];      // current proposed column per row
    __shared__ int  sPtr[DOUT];      // next unused candidate
    __shared__ int  sSel[DOUT];      // committed column per row
    __shared__ float sLz[DOUT];
    __shared__ unsigned sMask[MASKW];
    __shared__ unsigned sPair[DOUT];
    __shared__ float sWf[BINS];      // fallback weights
    __shared__ u64  pC[16];          // pending composites
    __shared__ int  sCmd, sRrow, sI, sP;
    __shared__ float redV[8]; __shared__ int redI[8];

    const int tid = threadIdx.x;
    const int lid = tid & 31;
    const int wid = tid >> 5;

    // init per-row state (top4 + logZ merged in parallel by k_merge)
    {
        u64 cd0 = g_top4[tid * 4 + 0];
        cand[tid][0] = cd0;
        cand[tid][1] = g_top4[tid * 4 + 1];
        cand[tid][2] = g_top4[tid * 4 + 2];
        cand[tid][3] = g_top4[tid * 4 + 3];
        float lz = g_logZ[tid];
        sLz[tid]  = lz;
        sArg[tid] = (int)(0xffffffffu - (unsigned)(cd0 & 0xffffffffu));
        sPtr[tid] = 1;
        float key = unMono((unsigned)(cd0 >> 32)) - lz;
        sC[tid] = ((u64)monoKey(key) << 32) | (unsigned)(255 - tid);
    }
    for (int i = tid; i < MASKW; i += 256) sMask[i] = 0u;
    if (tid == 0) { sI = 0; sP = 0; sCmd = 0; }
    __syncthreads();

    // bitonic sort ascending (rank r lives at index 255-r)
    for (int k = 2; k <= 256; k <<= 1) {
        for (int j = k >> 1; j > 0; j >>= 1) {
            int ixj = tid ^ j;
            if (ixj > tid) {
                u64 a = sC[tid], b = sC[ixj];
                bool sw = ((tid & k) == 0) ? (a > b) : (a < b);
                if (sw) { sC[tid] = b; sC[ixj] = a; }
            }
            __syncthreads();
        }
    }

    // sweep
    while (true) {
        if (wid == 0) {
            int i = sI, P = sP;
            int cmd = 0;
            while (true) {
                i = __shfl_sync(0xffffffffu, i, 0);
                P = __shfl_sync(0xffffffffu, P, 0);
                if (i >= 256 && P == 0) { cmd = 2; break; }
                if (P == 0) {
                    // chunked commit of up to 32 ranks
                    int r = i + lid;
                    bool valid = r < 256;
                    u64 C = valid ? sC[255 - r] : 0ull;
                    int row = 255 - (int)(C & 0xffffffffu);
                    int a   = valid ? sArg[row] : -1;
                    bool bad = false;
                    unsigned validmask = __ballot_sync(0xffffffffu, valid);
                    unsigned peers = __match_any_sync(0xffffffffu, a) & validmask;
                    if (valid) {
                        bool masked = (sMask[a >> 5] >> (a & 31)) & 1u;
                        bool first  = (peers & ((1u << lid) - 1u)) == 0;
                        bad = masked || !first;
                    }
                    unsigned badmask = __ballot_sync(0xffffffffu, valid && bad);
                    int cb = badmask ? ((int)__ffs(badmask) - 1) : 32;
                    int ncommit = min(cb, 256 - i);
                    if (lid < ncommit) {
                        atomicOr(&sMask[a >> 5], 1u << (a & 31));
                        sSel[row] = a;
                    }
                    __syncwarp();
                    i += ncommit;
                    if (cb < 32 && i < 256) {
                        // rank i is bad: pop next candidate or fallback
                        u64 Cc = sC[255 - i];
                        int brow = 255 - (int)(Cc & 0xffffffffu);
                        i += 1;
                        int act = 0;
                        if (lid == 0) {
                            int ptr = sPtr[brow];
                            if (ptr < 4 && P < 15) {
                                u64 cd = cand[brow][ptr];
                                sPtr[brow] = ptr + 1;
                                sArg[brow] = (int)(0xffffffffu - (unsigned)(cd & 0xffffffffu));
                                float nk = unMono((unsigned)(cd >> 32)) - sLz[brow];
                                pC[P] = ((u64)monoKey(nk) << 32) | (unsigned)(255 - brow);
                                P = P + 1;
                            } else {
                                sRrow = brow;
                                act = 1;
                            }
                        }
                        act = __shfl_sync(0xffffffffu, act, 0);
                        if (act) { cmd = 1; break; }
                    }
                } else {
                    // serial merge: sorted head vs best pending (lane 0)
                    int act = 0;
                    if (lid == 0) {
                        bool haveS = i < 256;
                        u64 Cs = haveS ? sC[255 - i] : 0ull;
                        int bj = 0; u64 Cb = pC[0];
                        for (int j = 1; j < P; ++j)
                            if (pC[j] > Cb) { Cb = pC[j]; bj = j; }
                        bool pickP = !haveS || (Cb > Cs);
                        u64 C = pickP ? Cb : Cs;
                        int row = 255 - (int)(C & 0xffffffffu);
                        int a = sArg[row];
                        bool masked = (sMask[a >> 5] >> (a & 31)) & 1u;
                        if (pickP) { pC[bj] = pC[P - 1]; P--; }
                        else i++;
                        if (!masked) {
                            sMask[a >> 5] |= 1u << (a & 31);
                            sSel[row] = a;
                        } else {
                            int ptr = sPtr[row];
                            if (ptr < 4 && P < 15) {
                                u64 cd = cand[row][ptr];
                                sPtr[row] = ptr + 1;
                                sArg[row] = (int)(0xffffffffu - (unsigned)(cd & 0xffffffffu));
                                float nk = unMono((unsigned)(cd >> 32)) - sLz[row];
                                pC[P] = ((u64)monoKey(nk) << 32) | (unsigned)(255 - row);
                                P = P + 1;
                            } else {
                                sRrow = row;
                                act = 1;
                            }
                        }
                    }
                    act = __shfl_sync(0xffffffffu, act, 0);
                    if (act) { cmd = 1; break; }
                }
            }
            if (lid == 0) { sCmd = cmd; sI = i; sP = P; }
        }
        __syncthreads();
        if (sCmd == 2) break;

        // ---- fallback: exact recompute of row t over unmasked columns ----
        {
            const int row = sRrow;
            if (tid < BINS) sWf[tid] = tinyW[tid * DOUT + row];
            __syncthreads();
            float bv = negInf(); int bi = 0x7fffffff;
            for (int n = tid; n < N_FEAT; n += 256) {
                if (!((sMask[n >> 5] >> (n & 31)) & 1u)) {
                    const float* ur = u + (size_t)n * BINS;
                    float aE = 0.f, aO = 0.f;   // same even/odd order as FFMA2 GEMM
                    #pragma unroll
                    for (int k2 = 0; k2 < BINS / 2; ++k2) {
                        aE = fmaf(ur[2 * k2],     sWf[2 * k2],     aE);
                        aO = fmaf(ur[2 * k2 + 1], sWf[2 * k2 + 1], aO);
                    }
                    float m   = aE + aO;
                    float lal = fminf(fmaxf(m - g_sc[n], CLIP_LO), CLIP_HI);
                    float uu  = uniform[(size_t)row * N_FEAT + n];
                    float x   = neglog_acc(uu);
                    float gum = -__logf(x);
                    float t   = (LOG10A + lal + gum) * INV_T;
                    if (t > bv) { bv = t; bi = n; }
                }
            }
            warpReducePair(bv, bi);
            if (lid == 0) { redV[wid] = bv; redI[wid] = bi; }
            __syncthreads();
            if (tid < 32) {
                bv = (tid < 8) ? redV[tid] : negInf();
                bi = (tid < 8) ? redI[tid] : 0x7fffffff;
                warpReducePair(bv, bi);
                if (tid == 0) {
                    sArg[row] = bi;
                    sPtr[row] = 4;   // stays list-exhausted
                    float nk = bv - sLz[row];
                    pC[sP] = ((u64)monoKey(nk) << 32) | (unsigned)(255 - row);
                    sP = sP + 1;
                    sCmd = 0;
                }
            }
        }
        __syncthreads();
    }

    // epilogue: sort (y<<8 | d) ascending for gather locality
    __syncthreads();
    sPair[tid] = ((unsigned)sSel[tid] << 8) | (unsigned)tid;
    __syncthreads();
    for (int k = 2; k <= 256; k <<= 1) {
        for (int j = k >> 1; j > 0; j >>= 1) {
            int ixj = tid ^ j;
            if (ixj > tid) {
                unsigned a = sPair[tid], b = sPair[ixj];
                bool sw = ((tid & k) == 0) ? (a > b) : (a < b);
                if (sw) { sPair[tid] = b; sPair[ixj] = a; }
            }
            __syncthreads();
        }
    }
    g_pair[tid] = sPair[tid];
}

// ---------------------------------------------------------------------------
// Kernel 4: Y[b,d] = X[b, y] — one b-row per block (measured best vs GB=4/8).
// PDL: its 4096 blocks dispatch DURING the single-block k_select (chip is
// otherwise idle) and park at the sync, firing the instant select completes.
// ---------------------------------------------------------------------------
__global__ void __launch_bounds__(256)
k_gather(const float* __restrict__ X, float* __restrict__ Y)
{
    cudaGridDependencySynchronize();   // wait for k_select completion

    const unsigned p = g_pair[threadIdx.x];
    const int b = blockIdx.x;
    Y[(size_t)b * DOUT + (p & 255u)] = X[(size_t)b * N_FEAT + (p >> 8)];
}

extern "C" void kernel_launch(void* const* d_in, const int* in_sizes, int n_in,
                              void* d_out, int out_size)
{
    const float* X       = (const float*)d_in[0];
    const float* u       = (const float*)d_in[1];
    const float* tinyW   = (const float*)d_in[2];
    const float* uniform = (const float*)d_in[3];
    float* Y = (float*)d_out;

    const int smem = (TILE_N * BINS + DOUT * (TILE_N + 1) + TILE_N) * (int)sizeof(float);
    cudaFuncSetAttribute(k_compute_t, cudaFuncAttributeMaxDynamicSharedMemorySize, smem);

    k_compute_t<<<NBLK, 512, smem>>>(u, tinyW, uniform);

    // PDL launches: overlap launch/dispatch with predecessor tails.
    cudaLaunchAttribute pdl[1];
    pdl[0].id = cudaLaunchAttributeProgrammaticStreamSerialization;
    pdl[0].val.programmaticStreamSerializationAllowed = 1;

    {
        cudaLaunchConfig_t cfg = {};
        cfg.gridDim  = dim3(DOUT, 1, 1);
        cfg.blockDim = dim3(128, 1, 1);
        cfg.attrs = pdl; cfg.numAttrs = 1;
        cudaLaunchKernelEx(&cfg, k_merge);
    }
    {
        cudaLaunchConfig_t cfg = {};
        cfg.gridDim  = dim3(1, 1, 1);
        cfg.blockDim = dim3(256, 1, 1);
        cfg.attrs = pdl; cfg.numAttrs = 1;
        cudaLaunchKernelEx(&cfg, k_select, u, tinyW, uniform);
    }
    {
        cudaLaunchConfig_t cfg = {};
        cfg.gridDim  = dim3(BATCH, 1, 1);
        cfg.blockDim = dim3(256, 1, 1);
        cfg.attrs = pdl; cfg.numAttrs = 1;
        cudaLaunchKernelEx(&cfg, k_gather, X, Y);
    }
}